// round 4
// baseline (speedup 1.0000x reference)
#include <cuda_runtime.h>
#include <cstdint>
#include <cstddef>

#define BB   32
#define NN   1024
#define DIMV 512
#define HH   8
#define KDV  64
#define DV   256
#define DHV  2048
#define QKVV 3072

// ---------------- scratch (device globals; allocation-free) ----------------
__device__ float g_xn[(size_t)BB * NN * DIMV];        //  64 MB
__device__ float g_qkv[(size_t)BB * NN * QKVV];       // 384 MB
__device__ float g_av[(size_t)BB * NN * DHV];         // 256 MB (b, q, h, d)
__device__ float g_biasmat[(size_t)HH * NN * NN];     //  32 MB (h, q, k)

// ---------------- helpers ----------------
__device__ __forceinline__ uint32_t f2tf32(float x) {
    uint32_t r;
    asm("cvt.rna.tf32.f32 %0, %1;" : "=r"(r) : "f"(x));
    return r;
}

__device__ __forceinline__ void mma_tf32(float c[4], const uint32_t a[4],
                                         const uint32_t b[2]) {
    asm volatile(
        "mma.sync.aligned.m16n8k8.row.col.f32.tf32.tf32.f32 "
        "{%0,%1,%2,%3}, {%4,%5,%6,%7}, {%8,%9}, {%0,%1,%2,%3};\n"
        : "+f"(c[0]), "+f"(c[1]), "+f"(c[2]), "+f"(c[3])
        : "r"(a[0]), "r"(a[1]), "r"(a[2]), "r"(a[3]), "r"(b[0]), "r"(b[1]));
}

// ---------------- LayerNorm ----------------
__global__ void __launch_bounds__(128)
ln_kernel(const float* __restrict__ x, const float* __restrict__ gamma,
          const float* __restrict__ beta) {
    const int row = blockIdx.x;
    const int t = threadIdx.x;
    const float4 v = reinterpret_cast<const float4*>(x)[(size_t)row * (DIMV / 4) + t];
    float s  = v.x + v.y + v.z + v.w;
    float sq = v.x * v.x + v.y * v.y + v.z * v.z + v.w * v.w;
    #pragma unroll
    for (int o = 16; o > 0; o >>= 1) {
        s  += __shfl_xor_sync(0xffffffffu, s, o);
        sq += __shfl_xor_sync(0xffffffffu, sq, o);
    }
    __shared__ float ss[4], ssq[4];
    const int w = t >> 5, l = t & 31;
    if (l == 0) { ss[w] = s; ssq[w] = sq; }
    __syncthreads();
    if (t == 0) {
        float S  = ss[0] + ss[1] + ss[2] + ss[3];
        float SQ = ssq[0] + ssq[1] + ssq[2] + ssq[3];
        float mu = S * (1.0f / DIMV);
        float var = SQ * (1.0f / DIMV) - mu * mu;
        ss[0]  = mu;
        ssq[0] = rsqrtf(var + 1e-5f);
    }
    __syncthreads();
    const float mu = ss[0], rstd = ssq[0];
    const float4 g  = reinterpret_cast<const float4*>(gamma)[t];
    const float4 bt = reinterpret_cast<const float4*>(beta)[t];
    float4 o;
    o.x = (v.x - mu) * rstd * g.x + bt.x;
    o.y = (v.y - mu) * rstd * g.y + bt.y;
    o.z = (v.z - mu) * rstd * g.z + bt.z;
    o.w = (v.w - mu) * rstd * g.w + bt.w;
    reinterpret_cast<float4*>(g_xn)[(size_t)row * (DIMV / 4) + t] = o;
}

// ---------------- dense bias matrix ----------------
__global__ void __launch_bounds__(256)
biasmat_kernel(const float* __restrict__ biases, const int* __restrict__ bidx) {
    const int h = blockIdx.y;
    const size_t i = (size_t)blockIdx.x * 256 + threadIdx.x;
    g_biasmat[(size_t)h * NN * NN + i] = biases[h * 1024 + bidx[i]];
}

// ---------------- tf32 tensor-core GEMM (qkv + proj) ----------------
// MODE 0: g_xn @ qkv_w + qkv_b -> g_qkv ; MODE 3: g_av @ proj_w + proj_b -> out
template<int MODE>
__global__ void __launch_bounds__(256, 2)
mm_tf32(const float* __restrict__ Barg, float* __restrict__ Carg,
        const float* __restrict__ biasv) {
    constexpr int LDA  = (MODE == 0) ? DIMV : DHV;
    constexpr int LDB  = (MODE == 0) ? QKVV : DIMV;
    constexpr int LDC  = (MODE == 0) ? QKVV : DIMV;
    constexpr int KDIM = (MODE == 0) ? DIMV : DHV;

    __shared__ uint32_t As[128][36];
    __shared__ uint32_t Bs[32][136];

    const int tid = threadIdx.x;
    const int m0 = blockIdx.y * 128;
    const int n0 = blockIdx.x * 128;

    const float* Ap = (MODE == 0) ? g_xn : g_av;
    const float* Bp = Barg;
    float* Cp = (MODE == 0) ? g_qkv : Carg;

    const int wid = tid >> 5, lane = tid & 31;
    const int wm = wid >> 1, wn = wid & 1;
    const int grp = lane >> 2, qd = lane & 3;

    float acc[2][8][4] = {};

    for (int kt = 0; kt < KDIM; kt += 32) {
        {
            const int r = tid >> 3, c4 = (tid & 7) * 4;
            #pragma unroll
            for (int i = 0; i < 4; ++i) {
                const int rr = r + i * 32;
                const float4 v = *reinterpret_cast<const float4*>(
                    &Ap[(size_t)(m0 + rr) * LDA + kt + c4]);
                As[rr][c4 + 0] = f2tf32(v.x);
                As[rr][c4 + 1] = f2tf32(v.y);
                As[rr][c4 + 2] = f2tf32(v.z);
                As[rr][c4 + 3] = f2tf32(v.w);
            }
        }
        {
            const int r = tid >> 5, c4 = (tid & 31) * 4;
            #pragma unroll
            for (int i = 0; i < 4; ++i) {
                const int rr = r + i * 8;
                const float4 v = *reinterpret_cast<const float4*>(
                    &Bp[(size_t)(kt + rr) * LDB + n0 + c4]);
                Bs[rr][c4 + 0] = f2tf32(v.x);
                Bs[rr][c4 + 1] = f2tf32(v.y);
                Bs[rr][c4 + 2] = f2tf32(v.z);
                Bs[rr][c4 + 3] = f2tf32(v.w);
            }
        }
        __syncthreads();
        #pragma unroll
        for (int ks = 0; ks < 4; ++ks) {
            uint32_t af[2][4];
            #pragma unroll
            for (int mt = 0; mt < 2; ++mt) {
                const int mr = wm * 32 + mt * 16 + grp;
                const int kc = ks * 8 + qd;
                af[mt][0] = As[mr][kc];
                af[mt][1] = As[mr + 8][kc];
                af[mt][2] = As[mr][kc + 4];
                af[mt][3] = As[mr + 8][kc + 4];
            }
            uint32_t bf[8][2];
            #pragma unroll
            for (int nt = 0; nt < 8; ++nt) {
                const int nc = wn * 64 + nt * 8 + grp;
                bf[nt][0] = Bs[ks * 8 + qd][nc];
                bf[nt][1] = Bs[ks * 8 + qd + 4][nc];
            }
            #pragma unroll
            for (int mt = 0; mt < 2; ++mt)
                #pragma unroll
                for (int nt = 0; nt < 8; ++nt)
                    mma_tf32(acc[mt][nt], af[mt], bf[nt]);
        }
        __syncthreads();
    }

    #pragma unroll
    for (int mt = 0; mt < 2; ++mt) {
        #pragma unroll
        for (int nt = 0; nt < 8; ++nt) {
            const int r0 = m0 + wm * 32 + mt * 16 + grp;
            const int c0 = n0 + wn * 64 + nt * 8 + 2 * qd;
            const float b0 = biasv[c0], b1 = biasv[c0 + 1];
            *reinterpret_cast<float2*>(&Cp[(size_t)r0 * LDC + c0]) =
                make_float2(acc[mt][nt][0] + b0, acc[mt][nt][1] + b1);
            *reinterpret_cast<float2*>(&Cp[(size_t)(r0 + 8) * LDC + c0]) =
                make_float2(acc[mt][nt][2] + b0, acc[mt][nt][3] + b1);
        }
    }
}

// ---------------- fused flash attention ----------------
// grid (16 qtiles, 256 bz), 512 threads. q-tile 64, k-tile 128, head-dim 64,
// V-dim 256 processed in 4 chunks of 64.
// smem: Qs[64][68] | KP: Ks[128][68] aliased with Ps[64][132] | Vs[128][72]
#define QS_OFF 0
#define QS_STR 68
#define KP_OFF (64 * 68)
#define KS_STR 68
#define PS_STR 132
#define VS_OFF (KP_OFF + 128 * 68)
#define VS_STR 72
#define RED_OFF (VS_OFF + 128 * 72)
#define FLASH_SMEM ((RED_OFF + 3 * 64) * 4)

__global__ void __launch_bounds__(512)
flash_kernel() {
    extern __shared__ uint32_t sm[];
    uint32_t* Qs = sm + QS_OFF;
    uint32_t* KP = sm + KP_OFF;
    uint32_t* Vs = sm + VS_OFF;
    float* m_s   = reinterpret_cast<float*>(sm + RED_OFF);
    float* l_s   = m_s + 64;
    float* fac_s = m_s + 128;

    const int bz = blockIdx.y;
    const int b = bz >> 3, h = bz & 7;
    const int q0 = blockIdx.x * 64;
    const int t = threadIdx.x;
    const int wid = t >> 5, lane = t & 31;
    const int grp = lane >> 2, qd = lane & 3;
    const int wm = wid >> 2, wn = wid & 3;

    const float* qbase = g_qkv + (size_t)b * NN * QKVV + h * 384;
    const float* kbase = qbase + 64;
    const float* vbase = qbase + 128;
    const float* bm = g_biasmat + (size_t)h * NN * NN + (size_t)q0 * NN;

    // load Q tile (64 x 64) as tf32
    #pragma unroll
    for (int i = 0; i < 2; ++i) {
        const int f = t + i * 512;
        const int row = f >> 4, c4 = (f & 15) * 4;
        const float4 v = *reinterpret_cast<const float4*>(
            &qbase[(size_t)(q0 + row) * QKVV + c4]);
        *reinterpret_cast<uint4*>(&Qs[row * QS_STR + c4]) =
            make_uint4(f2tf32(v.x), f2tf32(v.y), f2tf32(v.z), f2tf32(v.w));
    }
    if (t < 64) { m_s[t] = -1e30f; l_s[t] = 0.0f; }

    float accO[4][2][4] = {};
    float4 rK[4], rV[4];
    #pragma unroll
    for (int i = 0; i < 4; ++i) {
        const int f = t + i * 512;
        const int key = f >> 4, c4 = (f & 15) * 4;
        rK[i] = *reinterpret_cast<const float4*>(&kbase[(size_t)key * QKVV + c4]);
    }
    __syncthreads();

    for (int kt = 0; kt < 8; ++kt) {
        __syncthreads();                       // Ps of prev k-tile fully consumed
        // store K tile [key][d]
        #pragma unroll
        for (int i = 0; i < 4; ++i) {
            const int f = t + i * 512;
            const int key = f >> 4, c4 = (f & 15) * 4;
            *reinterpret_cast<uint4*>(&KP[key * KS_STR + c4]) =
                make_uint4(f2tf32(rK[i].x), f2tf32(rK[i].y),
                           f2tf32(rK[i].z), f2tf32(rK[i].w));
        }
        __syncthreads();
        // prefetch V chunk 0
        #pragma unroll
        for (int i = 0; i < 4; ++i) {
            const int f = t + i * 512;
            const int key = f >> 4, c4 = (f & 15) * 4;
            rV[i] = *reinterpret_cast<const float4*>(
                &vbase[(size_t)(kt * 128 + key) * QKVV + c4]);
        }
        // S = Q @ K^T  (64 x 128)
        float accS[4][4] = {};
        #pragma unroll
        for (int ks = 0; ks < 8; ++ks) {
            uint32_t a[4];
            const int mr = wm * 16 + grp;
            const int kc = ks * 8 + qd;
            a[0] = Qs[mr * QS_STR + kc];
            a[1] = Qs[(mr + 8) * QS_STR + kc];
            a[2] = Qs[mr * QS_STR + kc + 4];
            a[3] = Qs[(mr + 8) * QS_STR + kc + 4];
            #pragma unroll
            for (int nt = 0; nt < 4; ++nt) {
                const int nc = wn * 32 + nt * 8 + grp;
                uint32_t bf[2];
                bf[0] = KP[nc * KS_STR + kc];
                bf[1] = KP[nc * KS_STR + kc + 4];
                mma_tf32(accS[nt], a, bf);
            }
        }
        __syncthreads();                       // done reading Ks (alias with Ps)
        // store S*scale + bias to Ps (fp32)
        {
            const int r0 = wm * 16 + grp;
            #pragma unroll
            for (int nt = 0; nt < 4; ++nt) {
                const int c0 = wn * 32 + nt * 8 + 2 * qd;
                const float2 b0 = *reinterpret_cast<const float2*>(
                    &bm[(size_t)r0 * NN + kt * 128 + c0]);
                const float2 b1 = *reinterpret_cast<const float2*>(
                    &bm[(size_t)(r0 + 8) * NN + kt * 128 + c0]);
                *reinterpret_cast<float2*>(&KP[r0 * PS_STR + c0]) =
                    make_float2(accS[nt][0] * 0.125f + b0.x,
                                accS[nt][1] * 0.125f + b0.y);
                *reinterpret_cast<float2*>(&KP[(r0 + 8) * PS_STR + c0]) =
                    make_float2(accS[nt][2] * 0.125f + b1.x,
                                accS[nt][3] * 0.125f + b1.y);
            }
        }
        __syncthreads();
        // online softmax: warp wid owns rows wid, wid+16, wid+32, wid+48
        #pragma unroll
        for (int r = 0; r < 4; ++r) {
            const int row = wid + r * 16;
            float4 v = *reinterpret_cast<float4*>(&KP[row * PS_STR + lane * 4]);
            float mx = fmaxf(fmaxf(v.x, v.y), fmaxf(v.z, v.w));
            #pragma unroll
            for (int o = 16; o > 0; o >>= 1)
                mx = fmaxf(mx, __shfl_xor_sync(0xffffffffu, mx, o));
            const float mo = m_s[row];
            const float mn = fmaxf(mo, mx);
            const float p0 = __expf(v.x - mn), p1 = __expf(v.y - mn);
            const float p2 = __expf(v.z - mn), p3 = __expf(v.w - mn);
            float sum = p0 + p1 + p2 + p3;
            #pragma unroll
            for (int o = 16; o > 0; o >>= 1)
                sum += __shfl_xor_sync(0xffffffffu, sum, o);
            if (lane == 0) {
                const float fac = __expf(mo - mn);
                l_s[row] = l_s[row] * fac + sum;
                m_s[row] = mn;
                fac_s[row] = fac;
            }
            *reinterpret_cast<uint4*>(&KP[row * PS_STR + lane * 4]) =
                make_uint4(f2tf32(p0), f2tf32(p1), f2tf32(p2), f2tf32(p3));
        }
        __syncthreads();
        // rescale O accumulators
        {
            const int r0 = wm * 16 + grp;
            const float f0 = fac_s[r0], f1 = fac_s[r0 + 8];
            #pragma unroll
            for (int c = 0; c < 4; ++c)
                #pragma unroll
                for (int nt = 0; nt < 2; ++nt) {
                    accO[c][nt][0] *= f0; accO[c][nt][1] *= f0;
                    accO[c][nt][2] *= f1; accO[c][nt][3] *= f1;
                }
        }
        // O += P @ V, 4 chunks of 64 d
        for (int c = 0; c < 4; ++c) {
            __syncthreads();                   // Vs free
            #pragma unroll
            for (int i = 0; i < 4; ++i) {
                const int f = t + i * 512;
                const int key = f >> 4, c4 = (f & 15) * 4;
                *reinterpret_cast<uint4*>(&Vs[key * VS_STR + c4]) =
                    make_uint4(f2tf32(rV[i].x), f2tf32(rV[i].y),
                               f2tf32(rV[i].z), f2tf32(rV[i].w));
            }
            __syncthreads();
            if (c < 3) {
                #pragma unroll
                for (int i = 0; i < 4; ++i) {
                    const int f = t + i * 512;
                    const int key = f >> 4, c4 = (f & 15) * 4;
                    rV[i] = *reinterpret_cast<const float4*>(
                        &vbase[(size_t)(kt * 128 + key) * QKVV + (c + 1) * 64 + c4]);
                }
            } else if (kt < 7) {
                #pragma unroll
                for (int i = 0; i < 4; ++i) {
                    const int f = t + i * 512;
                    const int key = f >> 4, c4 = (f & 15) * 4;
                    rK[i] = *reinterpret_cast<const float4*>(
                        &kbase[(size_t)((kt + 1) * 128 + key) * QKVV + c4]);
                }
            }
            #pragma unroll
            for (int ks = 0; ks < 16; ++ks) {
                uint32_t a[4];
                const int r0 = wm * 16 + grp;
                const int k = ks * 8 + qd;
                a[0] = KP[r0 * PS_STR + k];
                a[1] = KP[(r0 + 8) * PS_STR + k];
                a[2] = KP[r0 * PS_STR + k + 4];
                a[3] = KP[(r0 + 8) * PS_STR + k + 4];
                #pragma unroll
                for (int nt = 0; nt < 2; ++nt) {
                    const int n = wn * 16 + nt * 8 + grp;
                    uint32_t bf[2];
                    bf[0] = Vs[(ks * 8 + qd) * VS_STR + n];
                    bf[1] = Vs[(ks * 8 + qd + 4) * VS_STR + n];
                    mma_tf32(accO[c][nt], a, bf);
                }
            }
        }
    }

    // final normalize + write
    const int r0 = wm * 16 + grp;
    const float inv0 = 1.0f / l_s[r0];
    const float inv1 = 1.0f / l_s[r0 + 8];
    float* obase = g_av + (size_t)b * NN * DHV + h * DV;
    #pragma unroll
    for (int c = 0; c < 4; ++c)
        #pragma unroll
        for (int nt = 0; nt < 2; ++nt) {
            const int col = c * 64 + wn * 16 + nt * 8 + 2 * qd;
            *reinterpret_cast<float2*>(
                &obase[(size_t)(q0 + r0) * DHV + col]) =
                make_float2(accO[c][nt][0] * inv0, accO[c][nt][1] * inv0);
            *reinterpret_cast<float2*>(
                &obase[(size_t)(q0 + r0 + 8) * DHV + col]) =
                make_float2(accO[c][nt][2] * inv1, accO[c][nt][3] * inv1);
        }
}

// ---------------- launch ----------------
extern "C" void kernel_launch(void* const* d_in, const int* in_sizes, int n_in,
                              void* d_out, int out_size) {
    (void)in_sizes; (void)n_in; (void)out_size;
    const float* x      = (const float*)d_in[0];
    const float* gamma  = (const float*)d_in[1];
    const float* beta   = (const float*)d_in[2];
    const float* qkv_w  = (const float*)d_in[3];
    const float* qkv_b  = (const float*)d_in[4];
    const float* proj_w = (const float*)d_in[5];
    const float* proj_b = (const float*)d_in[6];
    const float* biases = (const float*)d_in[7];
    const int*   bidx   = (const int*)d_in[8];
    float* out = (float*)d_out;

    cudaFuncSetAttribute(flash_kernel,
                         cudaFuncAttributeMaxDynamicSharedMemorySize, FLASH_SMEM);

    ln_kernel<<<BB * NN, 128>>>(x, gamma, beta);

    biasmat_kernel<<<dim3(NN * NN / 256, HH), 256>>>(biases, bidx);

    mm_tf32<0><<<dim3(QKVV / 128, (BB * NN) / 128), 256>>>(qkv_w, nullptr, qkv_b);

    flash_kernel<<<dim3(NN / 64, BB * HH), 512, FLASH_SMEM>>>();

    mm_tf32<3><<<dim3(DIMV / 128, (BB * NN) / 128), 256>>>(proj_w, out, proj_b);
}

// round 6
// speedup vs baseline: 1.3758x; 1.3758x over previous
#include <cuda_runtime.h>
#include <cstdint>
#include <cstddef>

#define BB   32
#define NN   1024
#define DIMV 512
#define HH   8
#define KDV  64
#define DV   256
#define DHV  2048
#define QKVV 3072

// ---------------- scratch (device globals; allocation-free) ----------------
__device__ float g_xn[(size_t)BB * NN * DIMV];        //  64 MB
__device__ float g_qkv[(size_t)BB * NN * QKVV];       // 384 MB
__device__ float g_attn[(size_t)BB * HH * NN * NN];   //   1 GB (bz, q, k)
__device__ float g_av[(size_t)BB * NN * DHV];         // 256 MB (b, q, h, d)
__device__ float g_biasmat[(size_t)HH * NN * NN];     //  32 MB (h, q, k)

// ---------------- helpers ----------------
__device__ __forceinline__ uint32_t f2tf32(float x) {
    uint32_t r;
    asm("cvt.rna.tf32.f32 %0, %1;" : "=r"(r) : "f"(x));
    return r;
}

__device__ __forceinline__ void mma_tf32(float c[4], const uint32_t a[4],
                                         const uint32_t b[2]) {
    asm volatile(
        "mma.sync.aligned.m16n8k8.row.col.f32.tf32.tf32.f32 "
        "{%0,%1,%2,%3}, {%4,%5,%6,%7}, {%8,%9}, {%0,%1,%2,%3};\n"
        : "+f"(c[0]), "+f"(c[1]), "+f"(c[2]), "+f"(c[3])
        : "r"(a[0]), "r"(a[1]), "r"(a[2]), "r"(a[3]), "r"(b[0]), "r"(b[1]));
}

__device__ __forceinline__ void cp16(void* smem_dst, const void* gsrc) {
    uint32_t d = (uint32_t)__cvta_generic_to_shared(smem_dst);
    asm volatile("cp.async.cg.shared.global [%0], [%1], 16;\n"
                 :: "r"(d), "l"(gsrc));
}
#define CP_COMMIT() asm volatile("cp.async.commit_group;\n" ::: "memory")
#define CP_WAIT1()  asm volatile("cp.async.wait_group 1;\n" ::: "memory")

// ---------------- LayerNorm ----------------
__global__ void __launch_bounds__(128)
ln_kernel(const float* __restrict__ x, const float* __restrict__ gamma,
          const float* __restrict__ beta) {
    const int row = blockIdx.x;
    const int t = threadIdx.x;
    const float4 v = reinterpret_cast<const float4*>(x)[(size_t)row * (DIMV / 4) + t];
    float s  = v.x + v.y + v.z + v.w;
    float sq = v.x * v.x + v.y * v.y + v.z * v.z + v.w * v.w;
    #pragma unroll
    for (int o = 16; o > 0; o >>= 1) {
        s  += __shfl_xor_sync(0xffffffffu, s, o);
        sq += __shfl_xor_sync(0xffffffffu, sq, o);
    }
    __shared__ float ss[4], ssq[4];
    const int w = t >> 5, l = t & 31;
    if (l == 0) { ss[w] = s; ssq[w] = sq; }
    __syncthreads();
    if (t == 0) {
        float S  = ss[0] + ss[1] + ss[2] + ss[3];
        float SQ = ssq[0] + ssq[1] + ssq[2] + ssq[3];
        float mu = S * (1.0f / DIMV);
        float var = SQ * (1.0f / DIMV) - mu * mu;
        ss[0]  = mu;
        ssq[0] = rsqrtf(var + 1e-5f);
    }
    __syncthreads();
    const float mu = ss[0], rstd = ssq[0];
    const float4 g  = reinterpret_cast<const float4*>(gamma)[t];
    const float4 bt = reinterpret_cast<const float4*>(beta)[t];
    float4 o;
    o.x = (v.x - mu) * rstd * g.x + bt.x;
    o.y = (v.y - mu) * rstd * g.y + bt.y;
    o.z = (v.z - mu) * rstd * g.z + bt.z;
    o.w = (v.w - mu) * rstd * g.w + bt.w;
    reinterpret_cast<float4*>(g_xn)[(size_t)row * (DIMV / 4) + t] = o;
}

// ---------------- dense bias matrix ----------------
__global__ void __launch_bounds__(256)
biasmat_kernel(const float* __restrict__ biases, const int* __restrict__ bidx) {
    const int h = blockIdx.y;
    const size_t i = (size_t)blockIdx.x * 256 + threadIdx.x;
    g_biasmat[(size_t)h * NN * NN + i] = biases[h * 1024 + bidx[i]];
}

// ---------------- unified tf32 tensor-core GEMM, cp.async pipelined ----------
// Tile BM=128, BN=128, BK=32; 256 threads, 8 warps (4M x 2N), warp tile 32x64.
// 2-stage cp.async double buffer; fp32 in smem; tf32 cvt at fragment load.
// A stage: [128][36] floats.  B stage: TRANSB ? [128][36] : [32][136].
// MODE 0: g_xn @ qkv_w + qkv_b -> g_qkv
// MODE 1: per bz: Q @ K^T * 0.125 + biasmat -> g_attn   (B = K rows [key][d])
// MODE 2: per bz: attn @ V -> g_av
// MODE 3: g_av @ proj_w + proj_b -> out
#define AS_ELEMS (128 * 36)
#define STAGE_ELEMS (AS_ELEMS + 4608)   // B region padded to 4608 for both shapes
#define MM_SMEM (2 * STAGE_ELEMS * 4)

template<int MODE>
__global__ void __launch_bounds__(256, 2)
mm_tf32(const float* __restrict__ Barg, float* __restrict__ Carg,
        const float* __restrict__ biasv) {
    constexpr int  LDA    = (MODE == 0) ? DIMV : (MODE == 1) ? QKVV
                          : (MODE == 2) ? NN   : DHV;
    constexpr int  LDB    = (MODE == 0) ? QKVV : (MODE == 1) ? QKVV
                          : (MODE == 2) ? QKVV : DIMV;
    constexpr int  LDC    = (MODE == 0) ? QKVV : (MODE == 1) ? NN
                          : (MODE == 2) ? DHV  : DIMV;
    constexpr int  KDIM   = (MODE == 0) ? DIMV : (MODE == 1) ? KDV
                          : (MODE == 2) ? NN   : DHV;
    constexpr bool TRANSB = (MODE == 1);
    constexpr int  NK     = KDIM / 32;

    extern __shared__ float sm[];

    const int tid = threadIdx.x;
    const int m0 = blockIdx.y * 128;
    const int n0 = blockIdx.x * 128;

    const float* Ap;
    const float* Bp;
    float* Cp;
    const float* bmp = nullptr;
    if (MODE == 0) {
        Ap = g_xn; Bp = Barg; Cp = g_qkv;
    } else if (MODE == 1) {
        const int bz = blockIdx.z, b = bz >> 3, h = bz & 7;
        Ap = g_qkv + (size_t)b * NN * QKVV + h * 384;          // Q
        Bp = g_qkv + (size_t)b * NN * QKVV + h * 384 + 64;     // K (rows)
        Cp = g_attn + (size_t)bz * NN * NN;
        bmp = g_biasmat + (size_t)h * NN * NN;
    } else if (MODE == 2) {
        const int bz = blockIdx.z, b = bz >> 3, h = bz & 7;
        Ap = g_attn + (size_t)bz * NN * NN;
        Bp = g_qkv + (size_t)b * NN * QKVV + h * 384 + 128;    // V
        Cp = g_av + (size_t)b * NN * DHV + h * DV;
    } else {
        Ap = g_av; Bp = Barg; Cp = Carg;
    }

    const int wid = tid >> 5, lane = tid & 31;
    const int wm = wid >> 1, wn = wid & 1;
    const int grp = lane >> 2, qd = lane & 3;

    // per-thread copy coordinates (4 x 16B chunks each for A and B)
    const int ar = tid >> 3, ac = (tid & 7) * 4;               // A: +32 rows/iter
    const int br_n = tid >> 5, bc_n = (tid & 31) * 4;          // B !trans: +8 rows
    const int br_t = tid >> 3, bc_t = (tid & 7) * 4;           // B trans:  +32 rows

    auto issue_tile = [&](int kt) {
        const int stg = kt & 1;
        float* As = sm + stg * STAGE_ELEMS;
        float* Bs = As + AS_ELEMS;
        const int k0 = kt * 32;
        #pragma unroll
        for (int i = 0; i < 4; ++i) {
            const int r = ar + i * 32;
            cp16(&As[r * 36 + ac], &Ap[(size_t)(m0 + r) * LDA + k0 + ac]);
        }
        if (TRANSB) {
            #pragma unroll
            for (int i = 0; i < 4; ++i) {
                const int r = br_t + i * 32;
                cp16(&Bs[r * 36 + bc_t], &Bp[(size_t)(n0 + r) * LDB + k0 + bc_t]);
            }
        } else {
            #pragma unroll
            for (int i = 0; i < 4; ++i) {
                const int r = br_n + i * 8;
                cp16(&Bs[r * 136 + bc_n], &Bp[(size_t)(k0 + r) * LDB + n0 + bc_n]);
            }
        }
    };

    float acc[2][8][4] = {};

    issue_tile(0); CP_COMMIT();
    if (NK > 1) issue_tile(1);
    CP_COMMIT();

    for (int kt = 0; kt < NK; ++kt) {
        CP_WAIT1();
        __syncthreads();
        const float* As = sm + (kt & 1) * STAGE_ELEMS;
        const float* Bs = As + AS_ELEMS;
        #pragma unroll
        for (int ks = 0; ks < 4; ++ks) {
            const int kc = ks * 8 + qd;
            uint32_t af[2][4];
            #pragma unroll
            for (int mt = 0; mt < 2; ++mt) {
                const int mr = wm * 32 + mt * 16 + grp;
                af[mt][0] = f2tf32(As[mr * 36 + kc]);
                af[mt][1] = f2tf32(As[(mr + 8) * 36 + kc]);
                af[mt][2] = f2tf32(As[mr * 36 + kc + 4]);
                af[mt][3] = f2tf32(As[(mr + 8) * 36 + kc + 4]);
            }
            uint32_t bf[8][2];
            #pragma unroll
            for (int nt = 0; nt < 8; ++nt) {
                const int nc = wn * 64 + nt * 8 + grp;
                if (TRANSB) {
                    bf[nt][0] = f2tf32(Bs[nc * 36 + kc]);
                    bf[nt][1] = f2tf32(Bs[nc * 36 + kc + 4]);
                } else {
                    bf[nt][0] = f2tf32(Bs[kc * 136 + nc]);
                    bf[nt][1] = f2tf32(Bs[(kc + 4) * 136 + nc]);
                }
            }
            #pragma unroll
            for (int mt = 0; mt < 2; ++mt)
                #pragma unroll
                for (int nt = 0; nt < 8; ++nt)
                    mma_tf32(acc[mt][nt], af[mt], bf[nt]);
        }
        __syncthreads();
        if (kt + 2 < NK) issue_tile(kt + 2);
        CP_COMMIT();
    }

    // --- epilogue ---
    #pragma unroll
    for (int mt = 0; mt < 2; ++mt) {
        #pragma unroll
        for (int nt = 0; nt < 8; ++nt) {
            const int r0 = m0 + wm * 32 + mt * 16 + grp;
            const int c0 = n0 + wn * 64 + nt * 8 + 2 * qd;
            float v0 = acc[mt][nt][0], v1 = acc[mt][nt][1];
            float v2 = acc[mt][nt][2], v3 = acc[mt][nt][3];
            if (MODE == 0 || MODE == 3) {
                const float b0 = biasv[c0], b1 = biasv[c0 + 1];
                v0 += b0; v1 += b1; v2 += b0; v3 += b1;
            } else if (MODE == 1) {
                const float2 bm0 = *reinterpret_cast<const float2*>(
                    &bmp[(size_t)r0 * NN + c0]);
                const float2 bm1 = *reinterpret_cast<const float2*>(
                    &bmp[(size_t)(r0 + 8) * NN + c0]);
                v0 = v0 * 0.125f + bm0.x; v1 = v1 * 0.125f + bm0.y;
                v2 = v2 * 0.125f + bm1.x; v3 = v3 * 0.125f + bm1.y;
            }
            *reinterpret_cast<float2*>(&Cp[(size_t)r0 * LDC + c0]) =
                make_float2(v0, v1);
            *reinterpret_cast<float2*>(&Cp[(size_t)(r0 + 8) * LDC + c0]) =
                make_float2(v2, v3);
        }
    }
}

// ---------------- softmax over k (in-place on g_attn) ----------------
__global__ void __launch_bounds__(256)
softmax_kernel() {
    const size_t base = (size_t)blockIdx.x * NN;
    float4* p = reinterpret_cast<float4*>(g_attn + base);
    const int t = threadIdx.x;
    const int w = t >> 5, l = t & 31;
    __shared__ float red[8];
    float4 v = p[t];
    float m = fmaxf(fmaxf(v.x, v.y), fmaxf(v.z, v.w));
    #pragma unroll
    for (int o = 16; o > 0; o >>= 1) m = fmaxf(m, __shfl_xor_sync(0xffffffffu, m, o));
    if (l == 0) red[w] = m;
    __syncthreads();
    if (t == 0) {
        float mm = red[0];
        #pragma unroll
        for (int i = 1; i < 8; ++i) mm = fmaxf(mm, red[i]);
        red[0] = mm;
    }
    __syncthreads();
    m = red[0];
    float4 e;
    e.x = __expf(v.x - m); e.y = __expf(v.y - m);
    e.z = __expf(v.z - m); e.w = __expf(v.w - m);
    float s = e.x + e.y + e.z + e.w;
    #pragma unroll
    for (int o = 16; o > 0; o >>= 1) s += __shfl_xor_sync(0xffffffffu, s, o);
    __syncthreads();
    if (l == 0) red[w] = s;
    __syncthreads();
    if (t == 0) {
        float tot = 0.f;
        #pragma unroll
        for (int i = 0; i < 8; ++i) tot += red[i];
        red[0] = tot;
    }
    __syncthreads();
    const float inv = 1.0f / red[0];
    e.x *= inv; e.y *= inv; e.z *= inv; e.w *= inv;
    p[t] = e;
}

// ---------------- launch ----------------
extern "C" void kernel_launch(void* const* d_in, const int* in_sizes, int n_in,
                              void* d_out, int out_size) {
    (void)in_sizes; (void)n_in; (void)out_size;
    const float* x      = (const float*)d_in[0];
    const float* gamma  = (const float*)d_in[1];
    const float* beta   = (const float*)d_in[2];
    const float* qkv_w  = (const float*)d_in[3];
    const float* qkv_b  = (const float*)d_in[4];
    const float* proj_w = (const float*)d_in[5];
    const float* proj_b = (const float*)d_in[6];
    const float* biases = (const float*)d_in[7];
    const int*   bidx   = (const int*)d_in[8];
    float* out = (float*)d_out;

    // idempotent, host-side, graph-capture-safe; no static guards
    cudaFuncSetAttribute(mm_tf32<0>, cudaFuncAttributeMaxDynamicSharedMemorySize, MM_SMEM);
    cudaFuncSetAttribute(mm_tf32<1>, cudaFuncAttributeMaxDynamicSharedMemorySize, MM_SMEM);
    cudaFuncSetAttribute(mm_tf32<2>, cudaFuncAttributeMaxDynamicSharedMemorySize, MM_SMEM);
    cudaFuncSetAttribute(mm_tf32<3>, cudaFuncAttributeMaxDynamicSharedMemorySize, MM_SMEM);

    ln_kernel<<<BB * NN, 128>>>(x, gamma, beta);

    biasmat_kernel<<<dim3(NN * NN / 256, HH), 256>>>(biases, bidx);

    // QKV: [32768 x 512] @ [512 x 3072]
    mm_tf32<0><<<dim3(QKVV / 128, (BB * NN) / 128), 256, MM_SMEM>>>(qkv_w, nullptr, qkv_b);

    // QK^T per (b,h): [1024 x 64] @ [64 x 1024]^T * scale + bias
    mm_tf32<1><<<dim3(NN / 128, NN / 128, BB * HH), 256, MM_SMEM>>>(nullptr, nullptr, nullptr);

    softmax_kernel<<<BB * HH * NN, 256>>>();

    // attn @ V per (b,h): [1024 x 1024] @ [1024 x 256]
    mm_tf32<2><<<dim3(DV / 128, NN / 128, BB * HH), 256, MM_SMEM>>>(nullptr, nullptr, nullptr);

    // proj: [32768 x 2048] @ [2048 x 512]
    mm_tf32<3><<<dim3(DIMV / 128, (BB * NN) / 128), 256, MM_SMEM>>>(proj_w, out, proj_b);
}